// round 1
// baseline (speedup 1.0000x reference)
#include <cuda_runtime.h>
#include <math.h>

// Problem constants
#define BSZ   32
#define NPAT  576
#define WCON  32
#define DDIM  256

// Scratch (no allocation allowed -> device globals)
__device__ float g_img[BSZ * NPAT * DDIM];   // normalized image tokens
__device__ float g_con[BSZ * WCON * DDIM];   // normalized concept vectors
__device__ float g_terms[BSZ * BSZ];         // per-(m,c) -log_sigmoid terms

// ---------------------------------------------------------------------------
// Row-wise L2 normalize: one warp per row of D=256 floats.
// which==0 -> write g_img, which==1 -> write g_con
// ---------------------------------------------------------------------------
__global__ void __launch_bounds__(256) normalize_kernel(const float* __restrict__ in,
                                                        int rows, int which) {
    int warp = (blockIdx.x * (blockDim.x >> 5)) + (threadIdx.x >> 5);
    int lane = threadIdx.x & 31;
    if (warp >= rows) return;

    const float4* ip = reinterpret_cast<const float4*>(in + (size_t)warp * DDIM);
    float4 v0 = ip[lane];
    float4 v1 = ip[lane + 32];
    float s = v0.x * v0.x + v0.y * v0.y + v0.z * v0.z + v0.w * v0.w
            + v1.x * v1.x + v1.y * v1.y + v1.z * v1.z + v1.w * v1.w;
#pragma unroll
    for (int o = 16; o > 0; o >>= 1)
        s += __shfl_xor_sync(0xffffffffu, s, o);

    float nrm = sqrtf(s);
    float r = 1.0f / fmaxf(nrm, 1e-12f);

    float* out = which ? g_con : g_img;
    float4* op = reinterpret_cast<float4*>(out + (size_t)warp * DDIM);
    v0.x *= r; v0.y *= r; v0.z *= r; v0.w *= r;
    v1.x *= r; v1.y *= r; v1.z *= r; v1.w *= r;
    op[lane]      = v0;
    op[lane + 32] = v1;
}

// ---------------------------------------------------------------------------
// Per-(m,c) block: compute max over patches of cos-sim for each concept w,
// then masked mean over valid concepts, then the log-sigmoid loss term.
// 256 threads = 8 warps; lane = concept index w; each warp handles 72 patches.
// Concepts of sample c live transposed in smem: con_s[d*33 + w] (pad 33 ->
// conflict-free). Image rows are read as uniform LDG.128 (broadcast, L1-hot).
// ---------------------------------------------------------------------------
__global__ void __launch_bounds__(256) sim_kernel(const int* __restrict__ lens,
                                                  const float* __restrict__ scale_p,
                                                  const float* __restrict__ bias_p) {
    const int m = blockIdx.x;
    const int c = blockIdx.y;
    const int tid  = threadIdx.x;
    const int wid  = tid >> 5;
    const int lane = tid & 31;

    __shared__ float con_s[DDIM * 33];      // [d][w] padded
    __shared__ float wmax_s[8][32];

    // load + transpose normalized concepts of sample c
    const float* conp = g_con + (size_t)c * WCON * DDIM;
#pragma unroll 4
    for (int i = tid; i < WCON * DDIM; i += 256) {
        int w = i >> 8;         // i / 256
        int d = i & 255;
        con_s[d * 33 + w] = conp[i];
    }
    __syncthreads();

    float wmax = -1e30f;
    const float* base = g_img + (size_t)m * NPAT * DDIM;

    const int n0 = wid * 72;
    for (int nb = n0; nb < n0 + 72; nb += 4) {
        const float4* a0 = reinterpret_cast<const float4*>(base + (nb + 0) * DDIM);
        const float4* a1 = reinterpret_cast<const float4*>(base + (nb + 1) * DDIM);
        const float4* a2 = reinterpret_cast<const float4*>(base + (nb + 2) * DDIM);
        const float4* a3 = reinterpret_cast<const float4*>(base + (nb + 3) * DDIM);

        float acc0 = 0.f, acc1 = 0.f, acc2 = 0.f, acc3 = 0.f;
#pragma unroll 8
        for (int k = 0; k < DDIM / 4; k++) {
            float4 x0 = a0[k];
            float4 x1 = a1[k];
            float4 x2 = a2[k];
            float4 x3 = a3[k];
            float b0 = con_s[(4 * k + 0) * 33 + lane];
            float b1 = con_s[(4 * k + 1) * 33 + lane];
            float b2 = con_s[(4 * k + 2) * 33 + lane];
            float b3 = con_s[(4 * k + 3) * 33 + lane];
            acc0 = fmaf(x0.x, b0, acc0); acc0 = fmaf(x0.y, b1, acc0);
            acc0 = fmaf(x0.z, b2, acc0); acc0 = fmaf(x0.w, b3, acc0);
            acc1 = fmaf(x1.x, b0, acc1); acc1 = fmaf(x1.y, b1, acc1);
            acc1 = fmaf(x1.z, b2, acc1); acc1 = fmaf(x1.w, b3, acc1);
            acc2 = fmaf(x2.x, b0, acc2); acc2 = fmaf(x2.y, b1, acc2);
            acc2 = fmaf(x2.z, b2, acc2); acc2 = fmaf(x2.w, b3, acc2);
            acc3 = fmaf(x3.x, b0, acc3); acc3 = fmaf(x3.y, b1, acc3);
            acc3 = fmaf(x3.z, b2, acc3); acc3 = fmaf(x3.w, b3, acc3);
        }
        wmax = fmaxf(wmax, acc0);
        wmax = fmaxf(wmax, acc1);
        wmax = fmaxf(wmax, acc2);
        wmax = fmaxf(wmax, acc3);
    }

    wmax_s[wid][lane] = wmax;
    __syncthreads();

    if (wid == 0) {
        float v = wmax_s[0][lane];
#pragma unroll
        for (int i = 1; i < 8; i++) v = fmaxf(v, wmax_s[i][lane]);

        int L = lens[c];
        float x = (lane < L) ? v : 0.f;
#pragma unroll
        for (int o = 16; o > 0; o >>= 1)
            x += __shfl_xor_sync(0xffffffffu, x, o);

        if (lane == 0) {
            float sim = x / (float)L;
            float t = expf(fminf(fmaxf(scale_p[0], -10.f), 10.f));
            float logit = fminf(fmaxf(t * sim + bias_p[0], -50.f), 50.f);
            float z = (m == c) ? 1.f : -1.f;
            float zx = z * logit;
            // stable log_sigmoid
            float ls = fminf(zx, 0.f) - log1pf(expf(-fabsf(zx)));
            g_terms[m * BSZ + c] = -ls;
        }
    }
}

// ---------------------------------------------------------------------------
// Deterministic reduction of the 1024 loss terms -> scalar mean.
// ---------------------------------------------------------------------------
__global__ void __launch_bounds__(256) reduce_kernel(float* __restrict__ out) {
    int tid = threadIdx.x;
    float s = 0.f;
#pragma unroll
    for (int i = 0; i < 4; i++) s += g_terms[tid + 256 * i];
#pragma unroll
    for (int o = 16; o > 0; o >>= 1)
        s += __shfl_xor_sync(0xffffffffu, s, o);

    __shared__ float red[8];
    if ((tid & 31) == 0) red[tid >> 5] = s;
    __syncthreads();
    if (tid == 0) {
        float tot = 0.f;
#pragma unroll
        for (int i = 0; i < 8; i++) tot += red[i];
        out[0] = tot * (1.0f / (BSZ * BSZ));
    }
}

extern "C" void kernel_launch(void* const* d_in, const int* in_sizes, int n_in,
                              void* d_out, int out_size) {
    const float* img  = nullptr;
    const float* con  = nullptr;
    const int*   lens = nullptr;
    const float* sc   = nullptr;
    const float* bi   = nullptr;

    for (int i = 0; i < n_in; i++) {
        int s = in_sizes[i];
        if (s == BSZ * NPAT * DDIM)      img = (const float*)d_in[i];
        else if (s == BSZ * WCON * DDIM) con = (const float*)d_in[i];
        else if (s == BSZ)               lens = (const int*)d_in[i];
        else if (s == 1) {
            if (!sc) sc = (const float*)d_in[i];   // logit_scale comes before logit_bias
            else     bi = (const float*)d_in[i];
        }
    }

    // Normalize: one warp per row (8 warps / block)
    normalize_kernel<<<(BSZ * NPAT + 7) / 8, 256>>>(img, BSZ * NPAT, 0);
    normalize_kernel<<<(BSZ * WCON + 7) / 8, 256>>>(con, BSZ * WCON, 1);

    dim3 grid(BSZ, BSZ);
    sim_kernel<<<grid, 256>>>(lens, sc, bi);

    reduce_kernel<<<1, 256>>>((float*)d_out);
}

// round 5
// speedup vs baseline: 15.6463x; 15.6463x over previous
#include <cuda_runtime.h>
#include <cuda_bf16.h>
#include <stdint.h>
#include <math.h>

#define BSZ   32
#define NPAT  576
#define WCON  32
#define DDIM  256
#define MROWS (BSZ*NPAT)   // 18432 patches
#define NCON  (BSZ*WCON)   // 1024 concepts

#define CT 128             // concepts per CTA tile (M)
#define PT 256             // patches per CTA tile (N)
#define NT_N (MROWS/PT)    // 72
#define NT_C (NCON/CT)     // 8

// scratch (device globals; no allocation allowed)
__device__ __nv_bfloat16 g_conb[NCON * DDIM];
__device__ __nv_bfloat16 g_imgb[MROWS * DDIM];
__device__ unsigned      g_enc[NCON * BSZ];     // running max[concept j][image m], encoded

// ---------------- helpers ----------------
static __device__ __forceinline__ uint32_t smem_u32(const void* p) {
    uint32_t a;
    asm("{ .reg .u64 t; cvta.to.shared.u64 t, %1; cvt.u32.u64 %0, t; }" : "=r"(a) : "l"(p));
    return a;
}
static __device__ __forceinline__ unsigned enc_f(float f) {
    unsigned b = __float_as_uint(f);
    return (b & 0x80000000u) ? ~b : (b | 0x80000000u);
}
static __device__ __forceinline__ float dec_f(unsigned u) {
    unsigned b = (u & 0x80000000u) ? (u & 0x7FFFFFFFu) : ~u;
    return __uint_as_float(b);
}
static __device__ __forceinline__ void cpasync16(uint32_t dst, const void* src) {
    asm volatile("cp.async.cg.shared.global [%0], [%1], 16;" :: "r"(dst), "l"(src));
}
static __device__ __forceinline__ void ldsm_x4(uint32_t* r, uint32_t addr) {
    asm volatile("ldmatrix.sync.aligned.m8n8.x4.shared.b16 {%0,%1,%2,%3}, [%4];"
                 : "=r"(r[0]), "=r"(r[1]), "=r"(r[2]), "=r"(r[3]) : "r"(addr));
}
static __device__ __forceinline__ void mma_bf16(float* c, const uint32_t* a, const uint32_t* b) {
    asm volatile("mma.sync.aligned.m16n8k16.row.col.f32.bf16.bf16.f32 "
                 "{%0,%1,%2,%3}, {%4,%5,%6,%7}, {%8,%9}, {%0,%1,%2,%3};"
                 : "+f"(c[0]), "+f"(c[1]), "+f"(c[2]), "+f"(c[3])
                 : "r"(a[0]), "r"(a[1]), "r"(a[2]), "r"(a[3]), "r"(b[0]), "r"(b[1]));
}

// ---------------------------------------------------------------------------
// L2-normalize rows of D=256 fp32, write bf16. One warp per row.
// ---------------------------------------------------------------------------
__global__ void __launch_bounds__(256) norm_kernel(const float* __restrict__ in,
                                                   int rows, int which) {
    int warp = blockIdx.x * 8 + (threadIdx.x >> 5);
    int lane = threadIdx.x & 31;
    if (warp >= rows) return;

    const float4* ip = reinterpret_cast<const float4*>(in + (size_t)warp * DDIM);
    float4 v0 = ip[lane];
    float4 v1 = ip[lane + 32];
    float s = v0.x*v0.x + v0.y*v0.y + v0.z*v0.z + v0.w*v0.w
            + v1.x*v1.x + v1.y*v1.y + v1.z*v1.z + v1.w*v1.w;
#pragma unroll
    for (int o = 16; o > 0; o >>= 1) s += __shfl_xor_sync(0xffffffffu, s, o);
    float r = 1.0f / fmaxf(sqrtf(s), 1e-12f);

    __nv_bfloat16* out = which ? g_conb : g_imgb;
    __nv_bfloat162* op = reinterpret_cast<__nv_bfloat162*>(out + (size_t)warp * DDIM);
    op[lane * 2 + 0]      = __floats2bfloat162_rn(v0.x * r, v0.y * r);
    op[lane * 2 + 1]      = __floats2bfloat162_rn(v0.z * r, v0.w * r);
    op[64 + lane * 2 + 0] = __floats2bfloat162_rn(v1.x * r, v1.y * r);
    op[64 + lane * 2 + 1] = __floats2bfloat162_rn(v1.z * r, v1.w * r);
}

__global__ void init_kernel() {
    int i = blockIdx.x * blockDim.x + threadIdx.x;
    if (i < NCON * BSZ) g_enc[i] = 0u;
}

// ---------------------------------------------------------------------------
// Fused GEMM + max-over-patches via mma.sync (HMMA).
// CTA: 128 concepts x 256 patches, K=256 in 4 chunks of 64, double-buffered.
// smem per buffer: A 128x128B (16KB), B 256x128B (32KB). 2 buffers = 96KB.
// 512 threads = 16 warps in 4(m) x 4(n); warp tile 32x64.
// ---------------------------------------------------------------------------
#define SMA_BYTES (CT * 128)
#define SMB_BYTES (PT * 128)
#define SMEM_DYN  (2 * (SMA_BYTES + SMB_BYTES))

static __device__ __forceinline__ void stage_chunk(int kc, uint32_t bufA, uint32_t bufB,
                                                   int ctile, int ptile, int tid) {
    const __nv_bfloat16* asrc = g_conb + (size_t)ctile * CT * DDIM + kc * 64;
    const __nv_bfloat16* bsrc = g_imgb + (size_t)ptile * PT * DDIM + kc * 64;
#pragma unroll
    for (int i = tid; i < 1024; i += 512) {           // A: 128 rows x 8 granules
        int r = i >> 3, s = i & 7;
        cpasync16(bufA + r * 128 + ((s ^ (r & 7)) << 4), asrc + (size_t)r * DDIM + s * 8);
    }
#pragma unroll
    for (int i = tid; i < 2048; i += 512) {           // B: 256 rows x 8 granules
        int r = i >> 3, s = i & 7;
        cpasync16(bufB + r * 128 + ((s ^ (r & 7)) << 4), bsrc + (size_t)r * DDIM + s * 8);
    }
    asm volatile("cp.async.commit_group;" ::: "memory");
}

static __device__ __forceinline__ void compute_chunk(float acc[2][8][4],
                                                     uint32_t bufA, uint32_t bufB,
                                                     int warp_m, int warp_n, int lane) {
#pragma unroll
    for (int ks = 0; ks < 4; ks++) {
        uint32_t a[2][4];
#pragma unroll
        for (int mi = 0; mi < 2; mi++) {
            int row = warp_m * 32 + mi * 16 + (lane & 15);
            uint32_t g = ((ks << 1) + (lane >> 4)) ^ (row & 7);
            ldsm_x4(a[mi], bufA + row * 128 + (g << 4));
        }
        uint32_t b[4][4];
#pragma unroll
        for (int pi = 0; pi < 4; pi++) {
            int nloc = warp_n * 64 + pi * 16 + ((lane >> 4) << 3) + (lane & 7);
            uint32_t g = ((ks << 1) + ((lane >> 3) & 1)) ^ (nloc & 7);
            ldsm_x4(b[pi], bufB + nloc * 128 + (g << 4));
        }
#pragma unroll
        for (int mi = 0; mi < 2; mi++)
#pragma unroll
            for (int pi = 0; pi < 4; pi++) {
                mma_bf16(acc[mi][2 * pi + 0], a[mi], &b[pi][0]);
                mma_bf16(acc[mi][2 * pi + 1], a[mi], &b[pi][2]);
            }
    }
}

__global__ void __launch_bounds__(512, 1) sim_mma_kernel() {
    extern __shared__ char sm[];
    const int ptile = blockIdx.x;
    const int ctile = blockIdx.y;
    const int tid = threadIdx.x;
    const int wid = tid >> 5;
    const int lane = tid & 31;
    const int warp_m = wid & 3;
    const int warp_n = wid >> 2;

    uint32_t A0 = smem_u32(sm);
    uint32_t A1 = A0 + SMA_BYTES;
    uint32_t B0 = A0 + 2 * SMA_BYTES;
    uint32_t B1 = B0 + SMB_BYTES;

    float acc[2][8][4];
#pragma unroll
    for (int mi = 0; mi < 2; mi++)
#pragma unroll
        for (int ni = 0; ni < 8; ni++)
#pragma unroll
            for (int c = 0; c < 4; c++) acc[mi][ni][c] = 0.f;

    stage_chunk(0, A0, B0, ctile, ptile, tid);
    stage_chunk(1, A1, B1, ctile, ptile, tid);

    asm volatile("cp.async.wait_group 1;" ::: "memory");
    __syncthreads();
    compute_chunk(acc, A0, B0, warp_m, warp_n, lane);
    __syncthreads();
    stage_chunk(2, A0, B0, ctile, ptile, tid);

    asm volatile("cp.async.wait_group 1;" ::: "memory");
    __syncthreads();
    compute_chunk(acc, A1, B1, warp_m, warp_n, lane);
    __syncthreads();
    stage_chunk(3, A1, B1, ctile, ptile, tid);

    asm volatile("cp.async.wait_group 1;" ::: "memory");
    __syncthreads();
    compute_chunk(acc, A0, B0, warp_m, warp_n, lane);

    asm volatile("cp.async.wait_group 0;" ::: "memory");
    __syncthreads();
    compute_chunk(acc, A1, B1, warp_m, warp_n, lane);

    // Epilogue: max over patch columns, split at image boundary, atomicMax.
    const int p0 = ptile * PT;
    const int m0 = p0 / NPAT;
    const int b  = (m0 + 1) * NPAT - p0;   // boundary (even; in (0, 576])
#pragma unroll
    for (int mi = 0; mi < 2; mi++) {
        float mx00 = -1e30f, mx01 = -1e30f;   // row half 0: part0/part1
        float mx10 = -1e30f, mx11 = -1e30f;   // row half 1
#pragma unroll
        for (int ni = 0; ni < 8; ni++) {
            int lc = warp_n * 64 + ni * 8 + (lane & 3) * 2;
            if (lc < b) {
                mx00 = fmaxf(mx00, fmaxf(acc[mi][ni][0], acc[mi][ni][1]));
                mx10 = fmaxf(mx10, fmaxf(acc[mi][ni][2], acc[mi][ni][3]));
            } else {
                mx01 = fmaxf(mx01, fmaxf(acc[mi][ni][0], acc[mi][ni][1]));
                mx11 = fmaxf(mx11, fmaxf(acc[mi][ni][2], acc[mi][ni][3]));
            }
        }
#pragma unroll
        for (int o = 1; o <= 2; o <<= 1) {
            mx00 = fmaxf(mx00, __shfl_xor_sync(0xffffffffu, mx00, o));
            mx01 = fmaxf(mx01, __shfl_xor_sync(0xffffffffu, mx01, o));
            mx10 = fmaxf(mx10, __shfl_xor_sync(0xffffffffu, mx10, o));
            mx11 = fmaxf(mx11, __shfl_xor_sync(0xffffffffu, mx11, o));
        }
        if ((lane & 3) == 0) {
            int r0 = ctile * CT + warp_m * 32 + mi * 16 + (lane >> 2);
            atomicMax(&g_enc[r0 * BSZ + m0],       enc_f(mx00));
            atomicMax(&g_enc[(r0 + 8) * BSZ + m0], enc_f(mx10));
            if (b < PT) {
                atomicMax(&g_enc[r0 * BSZ + m0 + 1],       enc_f(mx01));
                atomicMax(&g_enc[(r0 + 8) * BSZ + m0 + 1], enc_f(mx11));
            }
        }
    }
}

// ---------------------------------------------------------------------------
// Final: masked mean over ragged concepts + log-sigmoid + mean reduce.
// ---------------------------------------------------------------------------
__global__ void __launch_bounds__(1024) loss_kernel(const int* __restrict__ lens,
                                                    const float* __restrict__ scale_p,
                                                    const float* __restrict__ bias_p,
                                                    float* __restrict__ out) {
    int tid = threadIdx.x;
    int m = tid >> 5, c = tid & 31;
    int L = lens[c];
    float s = 0.f;
#pragma unroll
    for (int w = 0; w < WCON; w++) {
        if (w < L) s += dec_f(g_enc[((c << 5) + w) * BSZ + m]);
    }
    float sim = s / (float)L;
    float t = expf(fminf(fmaxf(scale_p[0], -10.f), 10.f));
    float logit = fminf(fmaxf(t * sim + bias_p[0], -50.f), 50.f);
    float z = (m == c) ? 1.f : -1.f;
    float zx = z * logit;
    float term = -(fminf(zx, 0.f) - log1pf(expf(-fabsf(zx))));

#pragma unroll
    for (int o = 16; o > 0; o >>= 1) term += __shfl_xor_sync(0xffffffffu, term, o);
    __shared__ float red[32];
    if ((tid & 31) == 0) red[tid >> 5] = term;
    __syncthreads();
    if (tid < 32) {
        float v = red[tid];
#pragma unroll
        for (int o = 16; o > 0; o >>= 1) v += __shfl_xor_sync(0xffffffffu, v, o);
        if (tid == 0) out[0] = v * (1.0f / (BSZ * BSZ));
    }
}

extern "C" void kernel_launch(void* const* d_in, const int* in_sizes, int n_in,
                              void* d_out, int out_size) {
    const float* img = nullptr; const float* con = nullptr;
    const int* lens = nullptr; const float* sc = nullptr; const float* bi = nullptr;
    for (int i = 0; i < n_in; i++) {
        int s = in_sizes[i];
        if (s == MROWS * DDIM)      img = (const float*)d_in[i];
        else if (s == NCON * DDIM)  con = (const float*)d_in[i];
        else if (s == BSZ)          lens = (const int*)d_in[i];
        else if (s == 1) { if (!sc) sc = (const float*)d_in[i]; else bi = (const float*)d_in[i]; }
    }

    cudaFuncSetAttribute(sim_mma_kernel, cudaFuncAttributeMaxDynamicSharedMemorySize, SMEM_DYN);

    norm_kernel<<<(MROWS + 7) / 8, 256>>>(img, MROWS, 0);
    norm_kernel<<<(NCON + 7) / 8, 256>>>(con, NCON, 1);
    init_kernel<<<(NCON * BSZ + 255) / 256, 256>>>();

    dim3 grid(NT_N, NT_C);
    sim_mma_kernel<<<grid, 512, SMEM_DYN>>>();

    loss_kernel<<<1, 1024>>>(lens, sc, bi, (float*)d_out);
}

// round 7
// speedup vs baseline: 16.2699x; 1.0399x over previous
#include <cuda_runtime.h>
#include <cuda_bf16.h>
#include <stdint.h>
#include <math.h>

#define BSZ   32
#define NPAT  576
#define WCON  32
#define DDIM  256
#define MROWS (BSZ*NPAT)   // 18432 patches
#define NCON  (BSZ*WCON)   // 1024 concepts

#define CT 128             // concepts per CTA tile (M)
#define PT 256             // patches per tile (N)
#define NT_N (MROWS/PT)    // 72 patch tiles
#define NT_C (NCON/CT)     // 8 concept tiles
#define PPG  4             // patch tiles per CTA
#define NPG  (NT_N/PPG)    // 18 patch groups -> grid 8 x 18 = 144 CTAs (1 wave)

// scratch (device globals; no allocation allowed)
__device__ __nv_bfloat16 g_conb[NCON * DDIM];
__device__ __nv_bfloat16 g_imgb[MROWS * DDIM];
__device__ unsigned      g_enc[NCON * BSZ];     // running max[concept j][image m], encoded

// ---------------- helpers ----------------
static __device__ __forceinline__ uint32_t smem_u32(const void* p) {
    uint32_t a;
    asm("{ .reg .u64 t; cvta.to.shared.u64 t, %1; cvt.u32.u64 %0, t; }" : "=r"(a) : "l"(p));
    return a;
}
static __device__ __forceinline__ unsigned enc_f(float f) {
    unsigned b = __float_as_uint(f);
    return (b & 0x80000000u) ? ~b : (b | 0x80000000u);
}
static __device__ __forceinline__ float dec_f(unsigned u) {
    unsigned b = (u & 0x80000000u) ? (u & 0x7FFFFFFFu) : ~u;
    return __uint_as_float(b);
}
static __device__ __forceinline__ void cpasync16(uint32_t dst, const void* src) {
    asm volatile("cp.async.cg.shared.global [%0], [%1], 16;" :: "r"(dst), "l"(src));
}
static __device__ __forceinline__ void ldsm_x4(uint32_t* r, uint32_t addr) {
    asm volatile("ldmatrix.sync.aligned.m8n8.x4.shared.b16 {%0,%1,%2,%3}, [%4];"
                 : "=r"(r[0]), "=r"(r[1]), "=r"(r[2]), "=r"(r[3]) : "r"(addr));
}
static __device__ __forceinline__ void mma_bf16(float* c, const uint32_t* a, const uint32_t* b) {
    asm volatile("mma.sync.aligned.m16n8k16.row.col.f32.bf16.bf16.f32 "
                 "{%0,%1,%2,%3}, {%4,%5,%6,%7}, {%8,%9}, {%0,%1,%2,%3};"
                 : "+f"(c[0]), "+f"(c[1]), "+f"(c[2]), "+f"(c[3])
                 : "r"(a[0]), "r"(a[1]), "r"(a[2]), "r"(a[3]), "r"(b[0]), "r"(b[1]));
}

// ---------------------------------------------------------------------------
// Fused: L2-normalize img+con rows (fp32 -> bf16), one warp per row, plus
// g_enc zero-init in the first 16 blocks. One launch instead of three.
// ---------------------------------------------------------------------------
__global__ void __launch_bounds__(256) prep_kernel(const float* __restrict__ img,
                                                   const float* __restrict__ con) {
    if (blockIdx.x < 16) {
        int idx = blockIdx.x * 2048 + threadIdx.x * 8;
#pragma unroll
        for (int k = 0; k < 8; k++) g_enc[idx + k] = 0u;
    }

    int gw = blockIdx.x * 8 + (threadIdx.x >> 5);
    int lane = threadIdx.x & 31;
    const float* in;
    __nv_bfloat16* out;
    int row;
    if (gw < MROWS)       { in = img; out = g_imgb; row = gw; }
    else if (gw < MROWS + NCON) { in = con; out = g_conb; row = gw - MROWS; }
    else return;

    const float4* ip = reinterpret_cast<const float4*>(in + (size_t)row * DDIM);
    float4 v0 = ip[lane];
    float4 v1 = ip[lane + 32];
    float s = v0.x*v0.x + v0.y*v0.y + v0.z*v0.z + v0.w*v0.w
            + v1.x*v1.x + v1.y*v1.y + v1.z*v1.z + v1.w*v1.w;
#pragma unroll
    for (int o = 16; o > 0; o >>= 1) s += __shfl_xor_sync(0xffffffffu, s, o);
    float r = 1.0f / fmaxf(sqrtf(s), 1e-12f);

    __nv_bfloat162* op = reinterpret_cast<__nv_bfloat162*>(out + (size_t)row * DDIM);
    op[lane * 2 + 0]      = __floats2bfloat162_rn(v0.x * r, v0.y * r);
    op[lane * 2 + 1]      = __floats2bfloat162_rn(v0.z * r, v0.w * r);
    op[64 + lane * 2 + 0] = __floats2bfloat162_rn(v1.x * r, v1.y * r);
    op[64 + lane * 2 + 1] = __floats2bfloat162_rn(v1.z * r, v1.w * r);
}

// ---------------------------------------------------------------------------
// Single-wave fused GEMM + max-over-patches.
// Grid (NPG, NT_C) = 144 CTAs, 512 threads (16 warps 4m x 4n, warp tile 32x64).
// A (128 concepts, full K=256) resident in smem (64KB, 4 chunks of 128x128B).
// B staged per (ptile, kchunk) into 2 x 32KB ring buffers.
// ---------------------------------------------------------------------------
#define SMA_CHUNK (CT * 128)           // 16KB per A k-chunk
#define SMA_BYTES (4 * SMA_CHUNK)      // 64KB
#define SMB_CHUNK (PT * 128)           // 32KB per B chunk buffer
#define SMEM_DYN  (SMA_BYTES + 2 * SMB_CHUNK)   // 128KB

static __device__ __forceinline__ void stage_B(int ptile, int kc, uint32_t buf, int tid) {
    const __nv_bfloat16* bsrc = g_imgb + (size_t)ptile * PT * DDIM + kc * 64;
#pragma unroll
    for (int i = tid; i < 2048; i += 512) {
        int r = i >> 3, s = i & 7;
        cpasync16(buf + r * 128 + ((s ^ (r & 7)) << 4), bsrc + (size_t)r * DDIM + s * 8);
    }
}

static __device__ __forceinline__ void compute_chunk(float acc[2][8][4],
                                                     uint32_t bufA, uint32_t bufB,
                                                     int warp_m, int warp_n, int lane) {
#pragma unroll
    for (int ks = 0; ks < 4; ks++) {
        uint32_t a[2][4];
#pragma unroll
        for (int mi = 0; mi < 2; mi++) {
            int row = warp_m * 32 + mi * 16 + (lane & 15);
            uint32_t g = ((ks << 1) + (lane >> 4)) ^ (row & 7);
            ldsm_x4(a[mi], bufA + row * 128 + (g << 4));
        }
        uint32_t b[4][4];
#pragma unroll
        for (int pi = 0; pi < 4; pi++) {
            int nloc = warp_n * 64 + pi * 16 + ((lane >> 4) << 3) + (lane & 7);
            uint32_t g = ((ks << 1) + ((lane >> 3) & 1)) ^ (nloc & 7);
            ldsm_x4(b[pi], bufB + nloc * 128 + (g << 4));
        }
#pragma unroll
        for (int mi = 0; mi < 2; mi++)
#pragma unroll
            for (int pi = 0; pi < 4; pi++) {
                mma_bf16(acc[mi][2 * pi + 0], a[mi], &b[pi][0]);
                mma_bf16(acc[mi][2 * pi + 1], a[mi], &b[pi][2]);
            }
    }
}

__global__ void __launch_bounds__(512, 1) sim_mma_kernel() {
    extern __shared__ char sm[];
    const int pgrp  = blockIdx.x;          // patch group (4 ptiles)
    const int ctile = blockIdx.y;
    const int tid = threadIdx.x;
    const int wid = tid >> 5;
    const int lane = tid & 31;
    const int warp_m = wid & 3;
    const int warp_n = wid >> 2;
    const int pt0 = pgrp * PPG;

    uint32_t A = smem_u32(sm);
    uint32_t B0 = A + SMA_BYTES;
    uint32_t B1 = B0 + SMB_CHUNK;

    // Stage resident A tile (all 4 k-chunks)
    {
        const __nv_bfloat16* asrc = g_conb + (size_t)ctile * CT * DDIM;
#pragma unroll
        for (int i = tid; i < 4096; i += 512) {
            int r = i >> 5, u = i & 31;
            int kc = u >> 3, s = u & 7;
            cpasync16(A + kc * SMA_CHUNK + r * 128 + ((s ^ (r & 7)) << 4),
                      asrc + (size_t)r * DDIM + kc * 64 + s * 8);
        }
        asm volatile("cp.async.commit_group;" ::: "memory");
    }
    // Prime B pipeline: (pt0, k0) and (pt0, k1)
    stage_B(pt0, 0, B0, tid);
    asm volatile("cp.async.commit_group;" ::: "memory");
    stage_B(pt0, 1, B1, tid);
    asm volatile("cp.async.commit_group;" ::: "memory");

    int t = 0;
    for (int p = 0; p < PPG; p++) {
        float acc[2][8][4];
#pragma unroll
        for (int mi = 0; mi < 2; mi++)
#pragma unroll
            for (int ni = 0; ni < 8; ni++)
#pragma unroll
                for (int c = 0; c < 4; c++) acc[mi][ni][c] = 0.f;

        for (int kc = 0; kc < 4; kc++, t++) {
            asm volatile("cp.async.wait_group 1;" ::: "memory");
            __syncthreads();
            uint32_t buf = (t & 1) ? B1 : B0;
            compute_chunk(acc, A + kc * SMA_CHUNK, buf, warp_m, warp_n, lane);
            __syncthreads();
            int tn = t + 2;
            if (tn < 4 * PPG) stage_B(pt0 + (tn >> 2), tn & 3, (tn & 1) ? B1 : B0, tid);
            asm volatile("cp.async.commit_group;" ::: "memory");
        }

        // Epilogue for ptile (overlaps with in-flight cp.async of next tile)
        const int ptile = pt0 + p;
        const int p0 = ptile * PT;
        const int m0 = p0 / NPAT;
        const int b  = (m0 + 1) * NPAT - p0;   // image boundary (even, in (0,576])
#pragma unroll
        for (int mi = 0; mi < 2; mi++) {
            float mx00 = -1e30f, mx01 = -1e30f;
            float mx10 = -1e30f, mx11 = -1e30f;
#pragma unroll
            for (int ni = 0; ni < 8; ni++) {
                int lc = warp_n * 64 + ni * 8 + (lane & 3) * 2;
                if (lc < b) {
                    mx00 = fmaxf(mx00, fmaxf(acc[mi][ni][0], acc[mi][ni][1]));
                    mx10 = fmaxf(mx10, fmaxf(acc[mi][ni][2], acc[mi][ni][3]));
                } else {
                    mx01 = fmaxf(mx01, fmaxf(acc[mi][ni][0], acc[mi][ni][1]));
                    mx11 = fmaxf(mx11, fmaxf(acc[mi][ni][2], acc[mi][ni][3]));
                }
            }
#pragma unroll
            for (int o = 1; o <= 2; o <<= 1) {
                mx00 = fmaxf(mx00, __shfl_xor_sync(0xffffffffu, mx00, o));
                mx01 = fmaxf(mx01, __shfl_xor_sync(0xffffffffu, mx01, o));
                mx10 = fmaxf(mx10, __shfl_xor_sync(0xffffffffu, mx10, o));
                mx11 = fmaxf(mx11, __shfl_xor_sync(0xffffffffu, mx11, o));
            }
            if ((lane & 3) == 0) {
                int r0 = ctile * CT + warp_m * 32 + mi * 16 + (lane >> 2);
                atomicMax(&g_enc[r0 * BSZ + m0],       enc_f(mx00));
                atomicMax(&g_enc[(r0 + 8) * BSZ + m0], enc_f(mx10));
                if (b < PT) {
                    atomicMax(&g_enc[r0 * BSZ + m0 + 1],       enc_f(mx01));
                    atomicMax(&g_enc[(r0 + 8) * BSZ + m0 + 1], enc_f(mx11));
                }
            }
        }
    }
}

// ---------------------------------------------------------------------------
// Final: masked mean over ragged concepts + log-sigmoid + mean reduce.
// ---------------------------------------------------------------------------
__global__ void __launch_bounds__(1024) loss_kernel(const int* __restrict__ lens,
                                                    const float* __restrict__ scale_p,
                                                    const float* __restrict__ bias_p,
                                                    float* __restrict__ out) {
    int tid = threadIdx.x;
    int m = tid >> 5, c = tid & 31;
    int L = lens[c];
    float s = 0.f;
#pragma unroll
    for (int w = 0; w < WCON; w++) {
        if (w < L) s += dec_f(g_enc[((c << 5) + w) * BSZ + m]);
    }
    float sim = s / (float)L;
    float t = expf(fminf(fmaxf(scale_p[0], -10.f), 10.f));
    float logit = fminf(fmaxf(t * sim + bias_p[0], -50.f), 50.f);
    float z = (m == c) ? 1.f : -1.f;
    float zx = z * logit;
    float term = -(fminf(zx, 0.f) - log1pf(expf(-fabsf(zx))));

#pragma unroll
    for (int o = 16; o > 0; o >>= 1) term += __shfl_xor_sync(0xffffffffu, term, o);
    __shared__ float red[32];
    if ((tid & 31) == 0) red[tid >> 5] = term;
    __syncthreads();
    if (tid < 32) {
        float v = red[tid];
#pragma unroll
        for (int o = 16; o > 0; o >>= 1) v += __shfl_xor_sync(0xffffffffu, v, o);
        if (tid == 0) out[0] = v * (1.0f / (BSZ * BSZ));
    }
}

extern "C" void kernel_launch(void* const* d_in, const int* in_sizes, int n_in,
                              void* d_out, int out_size) {
    const float* img = nullptr; const float* con = nullptr;
    const int* lens = nullptr; const float* sc = nullptr; const float* bi = nullptr;
    for (int i = 0; i < n_in; i++) {
        int s = in_sizes[i];
        if (s == MROWS * DDIM)      img = (const float*)d_in[i];
        else if (s == NCON * DDIM)  con = (const float*)d_in[i];
        else if (s == BSZ)          lens = (const int*)d_in[i];
        else if (s == 1) { if (!sc) sc = (const float*)d_in[i]; else bi = (const float*)d_in[i]; }
    }

    cudaFuncSetAttribute(sim_mma_kernel, cudaFuncAttributeMaxDynamicSharedMemorySize, SMEM_DYN);

    prep_kernel<<<(MROWS + NCON + 7) / 8, 256>>>(img, con);

    dim3 grid(NPG, NT_C);
    sim_mma_kernel<<<grid, 512, SMEM_DYN>>>();

    loss_kernel<<<1, 1024>>>(lens, sc, bi, (float*)d_out);
}